// round 2
// baseline (speedup 1.0000x reference)
#include <cuda_runtime.h>
#include <cuda_bf16.h>

// Problem constants (QMessagePassing: N nodes, E edges, F feats per quaternion component)
#define NN 50000
#define EE 800000
#define FF 16

// Scratch: numerator and denominator of the segment softmax, layout [c][n][f].
// 16B-aligned so red.global.add.v4.f32 is legal.
__device__ __align__(16) float g_num[4 * NN * FF];
__device__ __align__(16) float g_den[4 * NN * FF];

// ---------------------------------------------------------------------------
// Kernel 1: zero the softmax accumulators (must happen every launch)
// ---------------------------------------------------------------------------
__global__ void k_zero() {
    int i = blockIdx.x * blockDim.x + threadIdx.x;
    const int nf4 = (4 * NN * FF) / 4;
    if (i < nf4) {
        ((float4*)g_num)[i] = make_float4(0.f, 0.f, 0.f, 0.f);
        ((float4*)g_den)[i] = make_float4(0.f, 0.f, 0.f, 0.f);
    }
}

// Vector reduction: one 128-bit RED instead of four 32-bit ones.
__device__ __forceinline__ void red_add_v4(float* p, float a, float b, float c, float d) {
    asm volatile("red.global.add.v4.f32 [%0], {%1, %2, %3, %4};"
                 :: "l"(p), "f"(a), "f"(b), "f"(c), "f"(d) : "memory");
}

// ---------------------------------------------------------------------------
// Kernel 2: single-pass edge kernel.
// One thread per (component, edge, float4-of-features):
//   m = q[c, src, f] + edge_attr[c, e, f]
//   w = exp(beta * m)            (no max-subtraction: |z| <= ~9 in fp32, safe)
//   den[c, dst, f] += w ;  num[c, dst, f] += m * w
// edge_attr read is perfectly coalesced (tid*16B contiguous).
// ---------------------------------------------------------------------------
__global__ void __launch_bounds__(256) k_edge(const float* __restrict__ q,
                                              const float* __restrict__ ea,
                                              const int*   __restrict__ ei,
                                              const float* __restrict__ beta) {
    int tid = blockIdx.x * blockDim.x + threadIdx.x;
    const int total = 4 * EE * 4;          // c * e * f4
    if (tid >= total) return;

    int c   = tid / (EE * 4);
    int rem = tid - c * (EE * 4);
    int e   = rem >> 2;
    int f4  = rem & 3;

    int src = __ldg(&ei[e]);
    int dst = __ldg(&ei[EE + e]);
    float b = __ldg(beta);

    float4 a  = ((const float4*)ea)[tid];
    float4 qv = __ldg(&((const float4*)q)[(c * NN + src) * 4 + f4]);

    float m0 = a.x + qv.x;
    float m1 = a.y + qv.y;
    float m2 = a.z + qv.z;
    float m3 = a.w + qv.w;

    float w0 = __expf(b * m0);
    float w1 = __expf(b * m1);
    float w2 = __expf(b * m2);
    float w3 = __expf(b * m3);

    int base = (c * NN + dst) * FF + f4 * 4;
    red_add_v4(&g_den[base], w0, w1, w2, w3);
    red_add_v4(&g_num[base], m0 * w0, m1 * w1, m2 * w2, m3 * w3);
}

// ---------------------------------------------------------------------------
// Kernel 3: finalize softmax (agg = num/den), residual x = q + agg, then the
// 2-layer quaternion MLP. 256 threads = 4 nodes/block, 64 threads per node
// (thread idx within node = co*16 + fo).
// ---------------------------------------------------------------------------
__global__ void __launch_bounds__(256) k_mlp(const float* __restrict__ q,
                                             const float* __restrict__ W1,
                                             const float* __restrict__ b1,
                                             const float* __restrict__ W2,
                                             const float* __restrict__ b2,
                                             float*       __restrict__ out) {
    __shared__ float w1s[1024], w2s[1024], b1s[64], b2s[64];
    __shared__ float xs[4][64], hs[4][64];

    int t = threadIdx.x;
    for (int i = t; i < 1024; i += 256) { w1s[i] = W1[i]; w2s[i] = W2[i]; }
    if (t < 64) { b1s[t] = b1[t]; b2s[t] = b2[t]; }

    int nl   = t >> 6;          // node-in-block 0..3
    int idx  = t & 63;          // 0..63 within node
    int co   = idx >> 4;        // output quaternion component
    int fo   = idx & 15;        // output feature
    int node = blockIdx.x * 4 + nl;

    // Hamilton-product index tables: which W component and sign each
    // (c_out, c_in) pair uses.
    const int   mtab[4][4] = {{0,1,2,3},{1,0,3,2},{2,3,0,1},{3,2,1,0}};
    const float stab[4][4] = {{ 1.f,-1.f,-1.f,-1.f},
                              { 1.f, 1.f, 1.f,-1.f},
                              { 1.f,-1.f, 1.f, 1.f},
                              { 1.f, 1.f,-1.f, 1.f}};

    __syncthreads();

    if (node < NN) {
        int gi   = (co * NN + node) * FF + fo;
        float de = g_den[gi];
        float agg = (de > 0.f) ? g_num[gi] / de : 0.f;
        xs[nl][idx] = q[gi] + agg;
    }
    __syncthreads();

    if (node < NN) {
        float h = b1s[idx];
        #pragma unroll
        for (int ci = 0; ci < 4; ci++) {
            int   m = mtab[co][ci];
            float s = stab[co][ci];
            const float* wp = &w1s[m * 256 + fo];
            const float* xp = &xs[nl][ci * 16];
            #pragma unroll
            for (int fi = 0; fi < 16; fi++)
                h += s * xp[fi] * wp[fi * 16];
        }
        hs[nl][idx] = fmaxf(h, 0.f);
    }
    __syncthreads();

    if (node < NN) {
        float o = b2s[idx];
        #pragma unroll
        for (int ci = 0; ci < 4; ci++) {
            int   m = mtab[co][ci];
            float s = stab[co][ci];
            const float* wp = &w2s[m * 256 + fo];
            const float* hp = &hs[nl][ci * 16];
            #pragma unroll
            for (int fi = 0; fi < 16; fi++)
                o += s * hp[fi] * wp[fi * 16];
        }
        out[(co * NN + node) * FF + fo] = o;
    }
}

// ---------------------------------------------------------------------------
// Launch
// Inputs (metadata order): q, edge_attr, edge_index, W1, b1, W2, b2, beta
// ---------------------------------------------------------------------------
extern "C" void kernel_launch(void* const* d_in, const int* in_sizes, int n_in,
                              void* d_out, int out_size) {
    const float* q    = (const float*)d_in[0];
    const float* ea   = (const float*)d_in[1];
    const int*   ei   = (const int*)  d_in[2];
    const float* W1   = (const float*)d_in[3];
    const float* b1   = (const float*)d_in[4];
    const float* W2   = (const float*)d_in[5];
    const float* b2   = (const float*)d_in[6];
    const float* beta = (const float*)d_in[7];
    float* out = (float*)d_out;

    // 1) zero accumulators
    {
        int nf4 = (4 * NN * FF) / 4;
        k_zero<<<(nf4 + 255) / 256, 256>>>();
    }
    // 2) edge pass (single pass, fused exp + atomic num/den)
    {
        int total = 4 * EE * 4;
        k_edge<<<(total + 255) / 256, 256>>>(q, ea, ei, beta);
    }
    // 3) finalize + quaternion MLP
    {
        int blocks = (NN + 3) / 4;
        k_mlp<<<blocks, 256>>>(q, W1, b1, W2, b2, out);
    }
}